// round 5
// baseline (speedup 1.0000x reference)
#include <cuda_runtime.h>
#include <cstdint>

#define N_NODES 100000
#define N_EDGES 1600000
#define CH      128

// Scratch (static device globals — no allocation in kernel_launch)
__device__ __align__(16) float g_h[(size_t)N_NODES * CH];   // h = x W^T + b  (51.2 MB)
__device__ int   g_deg[N_NODES];       // in-degree incl. self-loop
__device__ float g_isd[N_NODES];       // deg^{-1/2}
__device__ int   g_row[N_NODES];       // CSR row_start (by dst, real edges only)
__device__ int   g_fill[N_NODES];      // fill cursors
__device__ int   g_csr[N_EDGES];       // src ids grouped by dst
__device__ int   g_any_hi;
__device__ int   g_is64;               // 1 if edge_index is int64

// ------------------------------------------------------ index dtype sniff ---
__global__ void k_sniff(const int* __restrict__ w) {
    int t = blockIdx.x * blockDim.x + threadIdx.x;     // 65536 threads
    int i = (int)(((long long)t * 1599983LL) % 1600000LL);
    if (w[2 * i + 1] != 0) g_any_hi = 1;
}
__global__ void k_sniff_init() { g_any_hi = 0; }
__global__ void k_sniff_fin()  { g_is64 = (g_any_hi == 0); }

__device__ __forceinline__ void edge_params(int* stride, int* dbase) {
    int f = g_is64;
    *stride = f ? 2 : 1;
    *dbase  = f ? 2 * N_EDGES : N_EDGES;
}

// ---------------------------------------------------------------- degree ----
__global__ void k_deg_init() {
    int i = blockIdx.x * blockDim.x + threadIdx.x;
    if (i < N_NODES) g_deg[i] = 1;            // self-loop
}

__global__ void k_deg_count(const int* __restrict__ ei) {
    int e = blockIdx.x * blockDim.x + threadIdx.x;
    if (e >= N_EDGES) return;
    int stride, dbase; edge_params(&stride, &dbase);
    atomicAdd(&g_deg[ei[dbase + stride * e]], 1);
}

__global__ void k_isd() {
    int i = blockIdx.x * blockDim.x + threadIdx.x;
    if (i < N_NODES) g_isd[i] = rsqrtf((float)g_deg[i]);
}

// ------------------------------------------------- CSR row-start (scan) -----
// Single block, 1024 threads; exclusive scan of (deg-1). Also zeroes cursors.
__global__ void __launch_bounds__(1024) k_scan() {
    __shared__ int part[1024];
    const int t   = threadIdx.x;
    const int PER = (N_NODES + 1023) / 1024;           // 98
    int s0 = t * PER;
    int e0 = min(s0 + PER, N_NODES);

    int sum = 0;
    for (int i = s0; i < e0; i++) sum += g_deg[i] - 1;
    part[t] = sum;
    __syncthreads();
    for (int off = 1; off < 1024; off <<= 1) {
        int v = (t >= off) ? part[t - off] : 0;
        __syncthreads();
        part[t] += v;
        __syncthreads();
    }
    int excl = (t == 0) ? 0 : part[t - 1];
    for (int i = s0; i < e0; i++) {
        g_row[i]  = excl;
        g_fill[i] = 0;
        excl += g_deg[i] - 1;
    }
}

// -------------------------------------------------------------- CSR fill ----
__global__ void k_fill(const int* __restrict__ ei) {
    int e = blockIdx.x * blockDim.x + threadIdx.x;
    if (e >= N_EDGES) return;
    int stride, dbase; edge_params(&stride, &dbase);
    int s = ei[stride * e];
    int d = ei[dbase + stride * e];
    int pos = atomicAdd(&g_fill[d], 1);
    g_csr[g_row[d] + pos] = s;
}

// ------------------------------------------------------------------ GEMM ----
__global__ void __launch_bounds__(256) k_gemm(const float* __restrict__ x,
                                              const float* __restrict__ W,
                                              const float* __restrict__ b) {
    __shared__ float xs[32][CH];
    __shared__ float wt[32][CH];   // wt[kk][o] = W[o][kc+kk]

    const int t    = threadIdx.x;
    const int w    = t >> 5;
    const int lane = t & 31;

    const float4* xg = (const float4*)(x + (size_t)blockIdx.x * 32 * CH);
    #pragma unroll
    for (int i = 0; i < 4; i++) {
        int v = t + i * 256;
        ((float4*)&xs[0][0])[v] = xg[v];
    }

    float4 bias = ((const float4*)b)[lane];
    float acc[4][4];
    #pragma unroll
    for (int ri = 0; ri < 4; ri++) {
        acc[ri][0] = bias.x; acc[ri][1] = bias.y;
        acc[ri][2] = bias.z; acc[ri][3] = bias.w;
    }

    const int o    = t & 127;
    const int half = t >> 7;

    for (int kc = 0; kc < CH; kc += 32) {
        __syncthreads();
        #pragma unroll
        for (int i = 0; i < 4; i++) {
            float4 f = *(const float4*)(W + (size_t)o * CH + kc + half * 16 + i * 4);
            int kk = half * 16 + i * 4;
            wt[kk + 0][o] = f.x;
            wt[kk + 1][o] = f.y;
            wt[kk + 2][o] = f.z;
            wt[kk + 3][o] = f.w;
        }
        __syncthreads();

        #pragma unroll
        for (int kk = 0; kk < 32; kk++) {
            float4 bv = *(const float4*)&wt[kk][lane * 4];
            #pragma unroll
            for (int ri = 0; ri < 4; ri++) {
                float a = xs[w * 4 + ri][kc + kk];
                acc[ri][0] += a * bv.x;
                acc[ri][1] += a * bv.y;
                acc[ri][2] += a * bv.z;
                acc[ri][3] += a * bv.w;
            }
        }
    }

    #pragma unroll
    for (int ri = 0; ri < 4; ri++) {
        size_t row = (size_t)blockIdx.x * 32 + w * 4 + ri;
        float4 st = make_float4(acc[ri][0], acc[ri][1], acc[ri][2], acc[ri][3]);
        ((float4*)g_h)[row * 32 + lane] = st;
    }
}

// -------------------------------------------------- fused gather-aggregate --
// One warp per node. acc = h[node]/deg (self-loop) + sum_{s in N_in(node)}
// h[s] * isd[s]*isd[node]. src ids + their isd preloaded 32 at a time and
// shfl-broadcast; inner loop unrolled x2 for MLP. Single float4 store per lane.
__global__ void __launch_bounds__(256) k_agg(float* __restrict__ out) {
    int node = (blockIdx.x << 3) + (threadIdx.x >> 5);
    int lane = threadIdx.x & 31;
    if (node >= N_NODES) return;

    int   deg   = g_deg[node];
    float isd_d = g_isd[node];
    float invd  = 1.0f / (float)deg;

    float4 hv = ((const float4*)g_h)[(size_t)node * 32 + lane];
    float4 acc = make_float4(hv.x * invd, hv.y * invd, hv.z * invd, hv.w * invd);

    int start = g_row[node];
    int m     = deg - 1;                     // real in-edges

    for (int base = 0; base < m; base += 32) {
        int cnt = min(32, m - base);
        int   sid = 0;
        float sv  = 0.f;
        if (lane < cnt) {
            sid = g_csr[start + base + lane];
            sv  = g_isd[sid];
        }
        int j = 0;
        for (; j + 1 < cnt; j += 2) {
            int   s0 = __shfl_sync(0xffffffffu, sid, j);
            float n0 = __shfl_sync(0xffffffffu, sv,  j) * isd_d;
            int   s1 = __shfl_sync(0xffffffffu, sid, j + 1);
            float n1 = __shfl_sync(0xffffffffu, sv,  j + 1) * isd_d;
            float4 a = ((const float4*)g_h)[(size_t)s0 * 32 + lane];
            float4 c = ((const float4*)g_h)[(size_t)s1 * 32 + lane];
            acc.x += a.x * n0; acc.y += a.y * n0;
            acc.z += a.z * n0; acc.w += a.w * n0;
            acc.x += c.x * n1; acc.y += c.y * n1;
            acc.z += c.z * n1; acc.w += c.w * n1;
        }
        if (j < cnt) {
            int   s0 = __shfl_sync(0xffffffffu, sid, j);
            float n0 = __shfl_sync(0xffffffffu, sv,  j) * isd_d;
            float4 a = ((const float4*)g_h)[(size_t)s0 * 32 + lane];
            acc.x += a.x * n0; acc.y += a.y * n0;
            acc.z += a.z * n0; acc.w += a.w * n0;
        }
    }

    ((float4*)out)[(size_t)node * 32 + lane] = acc;
}

// ------------------------------------------------------------------- glue ---
extern "C" void kernel_launch(void* const* d_in, const int* in_sizes, int n_in,
                              void* d_out, int out_size) {
    const float* x  = (const float*)d_in[0];
    const int*   ei = (const int*)d_in[1];     // int32 or int64 (sniffed)
    const float* W  = (const float*)d_in[2];
    const float* b  = (const float*)d_in[3];
    float* out = (float*)d_out;

    k_sniff_init<<<1, 1>>>();
    k_sniff<<<256, 256>>>(ei);
    k_sniff_fin<<<1, 1>>>();

    k_deg_init<<<(N_NODES + 255) / 256, 256>>>();
    k_deg_count<<<(N_EDGES + 255) / 256, 256>>>(ei);
    k_scan<<<1, 1024>>>();
    k_fill<<<(N_EDGES + 255) / 256, 256>>>(ei);
    k_gemm<<<N_NODES / 32, 256>>>(x, W, b);      // 100000 % 32 == 0
    k_isd<<<(N_NODES + 255) / 256, 256>>>();
    k_agg<<<(N_NODES + 7) / 8, 256>>>(out);
}

// round 6
// speedup vs baseline: 1.0737x; 1.0737x over previous
#include <cuda_runtime.h>
#include <cstdint>

#define N_NODES 100000
#define N_EDGES 1600000
#define CH      128

// Scratch (static device globals — no allocation in kernel_launch)
__device__ __align__(16) float g_h[(size_t)N_NODES * CH];   // h = x W^T + b  (51.2 MB)
__device__ int   g_deg[N_NODES];
__device__ float g_isd[N_NODES];              // deg^{-1/2}
__device__ int   g_any_hi;
__device__ int   g_is64;                      // 1 if edge_index is int64

// ------------------------------------------------------ index dtype sniff ---
__global__ void k_sniff(const int* __restrict__ w) {
    int t = blockIdx.x * blockDim.x + threadIdx.x;     // 65536 threads
    int i = (int)(((long long)t * 1599983LL) % 1600000LL);
    if (w[2 * i + 1] != 0) g_any_hi = 1;
}
__global__ void k_sniff_init() { g_any_hi = 0; }
__global__ void k_sniff_fin()  { g_is64 = (g_any_hi == 0); }

__device__ __forceinline__ void edge_params(int* stride, int* dbase) {
    int f = g_is64;
    *stride = f ? 2 : 1;
    *dbase  = f ? 2 * N_EDGES : N_EDGES;
}

// ---------------------------------------------------------------- degree ----
__global__ void k_deg_init() {
    int i = blockIdx.x * blockDim.x + threadIdx.x;
    if (i < N_NODES) g_deg[i] = 1;            // self-loop
}

__global__ void k_deg_count(const int* __restrict__ ei) {
    int e = blockIdx.x * blockDim.x + threadIdx.x;
    if (e >= N_EDGES) return;
    int stride, dbase; edge_params(&stride, &dbase);
    atomicAdd(&g_deg[ei[dbase + stride * e]], 1);
}

__global__ void k_isd() {
    int i = blockIdx.x * blockDim.x + threadIdx.x;
    if (i < N_NODES) g_isd[i] = rsqrtf((float)g_deg[i]);
}

// ------------------------------------------------------------------ GEMM ----
// h[m][o] = b[o] + sum_k x[m][k] * W[o][k]
// 256 threads, 32 rows/block; warp w -> rows 4w..4w+3, lane j -> cols 4j..4j+3.
// Inner product uses packed fma.rn.f32x2 (FFMA2): 8 fma-pipe issues per
// k-step/lane instead of 16, bit-identical fp32 rounding.
__global__ void __launch_bounds__(256) k_gemm(const float* __restrict__ x,
                                              const float* __restrict__ W,
                                              const float* __restrict__ b) {
    __shared__ float xs[32][CH];
    __shared__ float wt[32][CH];   // wt[kk][o] = W[o][kc+kk]

    const int t    = threadIdx.x;
    const int w    = t >> 5;
    const int lane = t & 31;

    const float4* xg = (const float4*)(x + (size_t)blockIdx.x * 32 * CH);
    #pragma unroll
    for (int i = 0; i < 4; i++) {
        int v = t + i * 256;
        ((float4*)&xs[0][0])[v] = xg[v];
    }

    float4 bias = ((const float4*)b)[lane];
    unsigned long long acc[4][2];       // 4 rows x 4 cols as f32x2 pairs
    #pragma unroll
    for (int ri = 0; ri < 4; ri++) {
        asm("mov.b64 %0, {%1, %2};" : "=l"(acc[ri][0])
            : "r"(__float_as_uint(bias.x)), "r"(__float_as_uint(bias.y)));
        asm("mov.b64 %0, {%1, %2};" : "=l"(acc[ri][1])
            : "r"(__float_as_uint(bias.z)), "r"(__float_as_uint(bias.w)));
    }

    const int o    = t & 127;
    const int half = t >> 7;

    for (int kc = 0; kc < CH; kc += 32) {
        __syncthreads();
        #pragma unroll
        for (int i = 0; i < 4; i++) {
            float4 f = *(const float4*)(W + (size_t)o * CH + kc + half * 16 + i * 4);
            int kk = half * 16 + i * 4;
            wt[kk + 0][o] = f.x;
            wt[kk + 1][o] = f.y;
            wt[kk + 2][o] = f.z;
            wt[kk + 3][o] = f.w;
        }
        __syncthreads();

        #pragma unroll
        for (int kk = 0; kk < 32; kk++) {
            ulonglong2 bv = *(const ulonglong2*)&wt[kk][lane * 4];  // 16B aligned
            #pragma unroll
            for (int ri = 0; ri < 4; ri++) {
                unsigned int au = __float_as_uint(xs[w * 4 + ri][kc + kk]);
                unsigned long long aa;
                asm("mov.b64 %0, {%1, %1};" : "=l"(aa) : "r"(au));
                asm("fma.rn.f32x2 %0, %1, %2, %0;" : "+l"(acc[ri][0])
                    : "l"(aa), "l"(bv.x));
                asm("fma.rn.f32x2 %0, %1, %2, %0;" : "+l"(acc[ri][1])
                    : "l"(aa), "l"(bv.y));
            }
        }
    }

    #pragma unroll
    for (int ri = 0; ri < 4; ri++) {
        unsigned int r0, r1, r2, r3;
        asm("mov.b64 {%0, %1}, %2;" : "=r"(r0), "=r"(r1) : "l"(acc[ri][0]));
        asm("mov.b64 {%0, %1}, %2;" : "=r"(r2), "=r"(r3) : "l"(acc[ri][1]));
        size_t row = (size_t)blockIdx.x * 32 + w * 4 + ri;
        float4 st = make_float4(__uint_as_float(r0), __uint_as_float(r1),
                                __uint_as_float(r2), __uint_as_float(r3));
        ((float4*)g_h)[row * 32 + lane] = st;
    }
}

// --------------------------------------------- self-loop init of output ----
__global__ void k_self(float* __restrict__ out) {
    int idx  = blockIdx.x * blockDim.x + threadIdx.x;   // N*32 threads
    int node = idx >> 5;
    int q    = idx & 31;
    float inv = 1.0f / (float)g_deg[node];
    float4 h  = ((const float4*)g_h)[(size_t)node * 32 + q];
    ((float4*)out)[(size_t)node * 32 + q] =
        make_float4(h.x * inv, h.y * inv, h.z * inv, h.w * inv);
}

// ------------------------------------------------------------ edge scatter --
// One warp per edge: gather h[src] (float4/lane), scale, vector red.add.v4
// into out[dst].
__global__ void __launch_bounds__(256) k_edges(const int* __restrict__ ei,
                                               float* __restrict__ out) {
    int e    = (blockIdx.x << 3) + (threadIdx.x >> 5);
    int lane = threadIdx.x & 31;
    if (e >= N_EDGES) return;

    int stride, dbase; edge_params(&stride, &dbase);
    int s = ei[stride * e];
    int d = ei[dbase + stride * e];
    float nrm = g_isd[s] * g_isd[d];

    float4 h = ((const float4*)g_h)[(size_t)s * 32 + lane];
    float* p = out + (size_t)d * CH + lane * 4;      // 16B aligned
    asm volatile("red.global.add.v4.f32 [%0], {%1, %2, %3, %4};"
                 :: "l"(p), "f"(h.x * nrm), "f"(h.y * nrm),
                    "f"(h.z * nrm), "f"(h.w * nrm)
                 : "memory");
}

// ------------------------------------------------------------------- glue ---
extern "C" void kernel_launch(void* const* d_in, const int* in_sizes, int n_in,
                              void* d_out, int out_size) {
    const float* x  = (const float*)d_in[0];
    const int*   ei = (const int*)d_in[1];     // int32 or int64 (sniffed)
    const float* W  = (const float*)d_in[2];
    const float* b  = (const float*)d_in[3];
    float* out = (float*)d_out;

    k_sniff_init<<<1, 1>>>();                    // launch 0
    k_sniff<<<256, 256>>>(ei);                   // launch 1
    k_sniff_fin<<<1, 1>>>();                     // launch 2
    k_gemm<<<N_NODES / 32, 256>>>(x, W, b);      // launch 3 (ncu-profiled slot)
    k_deg_init<<<(N_NODES + 255) / 256, 256>>>();
    k_deg_count<<<(N_EDGES + 255) / 256, 256>>>(ei);
    k_isd<<<(N_NODES + 255) / 256, 256>>>();
    k_self<<<(N_NODES * 32) / 256, 256>>>(out);
    k_edges<<<N_EDGES / 8, 256>>>(ei, out);
}

// round 7
// speedup vs baseline: 1.1501x; 1.0711x over previous
#include <cuda_runtime.h>
#include <cstdint>

#define N_NODES 100000
#define N_EDGES 1600000
#define CH      128

typedef unsigned long long ull;

// Scratch (static device globals — no allocation in kernel_launch)
__device__ __align__(16) float g_h[(size_t)N_NODES * CH];   // h = x W^T + b  (51.2 MB)
__device__ int   g_deg[N_NODES];
__device__ float g_isd[N_NODES];              // deg^{-1/2}
__device__ int   g_any_hi;
__device__ int   g_is64;                      // 1 if edge_index is int64

// ------------------------------------------------------ index dtype sniff ---
__global__ void k_sniff(const int* __restrict__ w) {
    int t = blockIdx.x * blockDim.x + threadIdx.x;     // 65536 threads
    int i = (int)(((long long)t * 1599983LL) % 1600000LL);
    if (w[2 * i + 1] != 0) g_any_hi = 1;
}
__global__ void k_sniff_init() { g_any_hi = 0; }
__global__ void k_sniff_fin()  { g_is64 = (g_any_hi == 0); }

__device__ __forceinline__ void edge_params(int* stride, int* dbase) {
    int f = g_is64;
    *stride = f ? 2 : 1;
    *dbase  = f ? 2 * N_EDGES : N_EDGES;
}

// ---------------------------------------------------------------- degree ----
__global__ void k_deg_init() {
    int i = blockIdx.x * blockDim.x + threadIdx.x;
    if (i < N_NODES) g_deg[i] = 1;            // self-loop
}

__global__ void k_deg_count(const int* __restrict__ ei) {
    int e = blockIdx.x * blockDim.x + threadIdx.x;
    if (e >= N_EDGES) return;
    int stride, dbase; edge_params(&stride, &dbase);
    atomicAdd(&g_deg[ei[dbase + stride * e]], 1);
}

__global__ void k_isd() {
    int i = blockIdx.x * blockDim.x + threadIdx.x;
    if (i < N_NODES) g_isd[i] = rsqrtf((float)g_deg[i]);
}

// ------------------------------------------------------------------ GEMM ----
// h[m][o] = b[o] + sum_k x[m][k] * W[o][k];  also out[m] = h[m]/deg[m] (fused
// self-loop init). 128 threads, 4 warps, 32 rows/block (grid 3125 exact).
// Microtile 8 rows x 4 cols per lane. a-operand loaded as broadcast LDS.128
// along k (4 k-steps per load); b as spread LDS.128. FFMA2 inner product.
__global__ void __launch_bounds__(128) k_gemm(const float* __restrict__ x,
                                              const float* __restrict__ W,
                                              const float* __restrict__ bias,
                                              float* __restrict__ out) {
    __shared__ float xs[32][CH];   // 16 KB input rows
    __shared__ float wt[32][CH];   // 16 KB: wt[kk][o] = W[o][kc+kk]

    const int t    = threadIdx.x;
    const int w    = t >> 5;       // 0..3
    const int lane = t & 31;

    // Load x tile (coalesced float4, 8 per thread)
    const float4* xg = (const float4*)(x + (size_t)blockIdx.x * 32 * CH);
    #pragma unroll
    for (int i = 0; i < 8; i++) {
        int v = t + i * 128;
        ((float4*)&xs[0][0])[v] = xg[v];
    }

    float4 b4 = ((const float4*)bias)[lane];
    ull acc[8][2];
    #pragma unroll
    for (int r = 0; r < 8; r++) {
        asm("mov.b64 %0, {%1, %2};" : "=l"(acc[r][0])
            : "r"(__float_as_uint(b4.x)), "r"(__float_as_uint(b4.y)));
        asm("mov.b64 %0, {%1, %2};" : "=l"(acc[r][1])
            : "r"(__float_as_uint(b4.z)), "r"(__float_as_uint(b4.w)));
    }

    for (int kc = 0; kc < CH; kc += 32) {
        __syncthreads();
        // thread t owns output row o=t: load its 32 k's, store transposed.
        // STS addresses = (i*4+j)*128 + t : consecutive t -> conflict-free.
        #pragma unroll
        for (int i = 0; i < 8; i++) {
            float4 f = *(const float4*)(W + (size_t)t * CH + kc + i * 4);
            wt[i * 4 + 0][t] = f.x;
            wt[i * 4 + 1][t] = f.y;
            wt[i * 4 + 2][t] = f.z;
            wt[i * 4 + 3][t] = f.w;
        }
        __syncthreads();

        #pragma unroll
        for (int g = 0; g < 8; g++) {          // 4 k-steps per group
            const int k0 = g * 4;
            ulonglong2 bq0 = *(const ulonglong2*)&wt[k0 + 0][lane * 4];
            ulonglong2 bq1 = *(const ulonglong2*)&wt[k0 + 1][lane * 4];
            ulonglong2 bq2 = *(const ulonglong2*)&wt[k0 + 2][lane * 4];
            ulonglong2 bq3 = *(const ulonglong2*)&wt[k0 + 3][lane * 4];
            #pragma unroll
            for (int r = 0; r < 8; r++) {
                float4 a = *(const float4*)&xs[w * 8 + r][kc + k0]; // broadcast
                ull a0, a1, a2, a3;
                asm("mov.b64 %0, {%1, %1};" : "=l"(a0) : "r"(__float_as_uint(a.x)));
                asm("mov.b64 %0, {%1, %1};" : "=l"(a1) : "r"(__float_as_uint(a.y)));
                asm("mov.b64 %0, {%1, %1};" : "=l"(a2) : "r"(__float_as_uint(a.z)));
                asm("mov.b64 %0, {%1, %1};" : "=l"(a3) : "r"(__float_as_uint(a.w)));
                asm("fma.rn.f32x2 %0, %1, %2, %0;" : "+l"(acc[r][0]) : "l"(a0), "l"(bq0.x));
                asm("fma.rn.f32x2 %0, %1, %2, %0;" : "+l"(acc[r][1]) : "l"(a0), "l"(bq0.y));
                asm("fma.rn.f32x2 %0, %1, %2, %0;" : "+l"(acc[r][0]) : "l"(a1), "l"(bq1.x));
                asm("fma.rn.f32x2 %0, %1, %2, %0;" : "+l"(acc[r][1]) : "l"(a1), "l"(bq1.y));
                asm("fma.rn.f32x2 %0, %1, %2, %0;" : "+l"(acc[r][0]) : "l"(a2), "l"(bq2.x));
                asm("fma.rn.f32x2 %0, %1, %2, %0;" : "+l"(acc[r][1]) : "l"(a2), "l"(bq2.y));
                asm("fma.rn.f32x2 %0, %1, %2, %0;" : "+l"(acc[r][0]) : "l"(a3), "l"(bq3.x));
                asm("fma.rn.f32x2 %0, %1, %2, %0;" : "+l"(acc[r][1]) : "l"(a3), "l"(bq3.y));
            }
        }
    }

    // Epilogue: write h and fused self-loop output out = h/deg.
    #pragma unroll
    for (int r = 0; r < 8; r++) {
        unsigned int r0, r1, r2, r3;
        asm("mov.b64 {%0, %1}, %2;" : "=r"(r0), "=r"(r1) : "l"(acc[r][0]));
        asm("mov.b64 {%0, %1}, %2;" : "=r"(r2), "=r"(r3) : "l"(acc[r][1]));
        float4 hv = make_float4(__uint_as_float(r0), __uint_as_float(r1),
                                __uint_as_float(r2), __uint_as_float(r3));
        size_t row = (size_t)blockIdx.x * 32 + w * 8 + r;
        ((float4*)g_h)[row * 32 + lane] = hv;
        float invd = 1.0f / (float)g_deg[row];
        ((float4*)out)[row * 32 + lane] =
            make_float4(hv.x * invd, hv.y * invd, hv.z * invd, hv.w * invd);
    }
}

// ------------------------------------------------------------ edge scatter --
// One warp per edge: gather h[src] (float4/lane), scale, vector red.add.v4
// into out[dst].
__global__ void __launch_bounds__(256) k_edges(const int* __restrict__ ei,
                                               float* __restrict__ out) {
    int e    = (blockIdx.x << 3) + (threadIdx.x >> 5);
    int lane = threadIdx.x & 31;
    if (e >= N_EDGES) return;

    int stride, dbase; edge_params(&stride, &dbase);
    int s = ei[stride * e];
    int d = ei[dbase + stride * e];
    float nrm = g_isd[s] * g_isd[d];

    float4 h = ((const float4*)g_h)[(size_t)s * 32 + lane];
    float* p = out + (size_t)d * CH + lane * 4;      // 16B aligned
    asm volatile("red.global.add.v4.f32 [%0], {%1, %2, %3, %4};"
                 :: "l"(p), "f"(h.x * nrm), "f"(h.y * nrm),
                    "f"(h.z * nrm), "f"(h.w * nrm)
                 : "memory");
}

// ------------------------------------------------------------------- glue ---
extern "C" void kernel_launch(void* const* d_in, const int* in_sizes, int n_in,
                              void* d_out, int out_size) {
    const float* x  = (const float*)d_in[0];
    const int*   ei = (const int*)d_in[1];     // int32 or int64 (sniffed)
    const float* W  = (const float*)d_in[2];
    const float* b  = (const float*)d_in[3];
    float* out = (float*)d_out;

    k_sniff_init<<<1, 1>>>();
    k_sniff<<<256, 256>>>(ei);
    k_sniff_fin<<<1, 1>>>();

    k_deg_init<<<(N_NODES + 255) / 256, 256>>>();
    k_deg_count<<<(N_EDGES + 255) / 256, 256>>>(ei);
    k_isd<<<(N_NODES + 255) / 256, 256>>>();
    k_gemm<<<N_NODES / 32, 128>>>(x, W, b, out);   // 3125 blocks, fused self
    k_edges<<<N_EDGES / 8, 256>>>(ei, out);
}